// round 9
// baseline (speedup 1.0000x reference)
#include <cuda_runtime.h>

#define NG  8     // graphs
#define NN  128   // nodes
#define DIM 128   // embedding dim
#define NE  128   // edge types
#define VEC 300   // word-vec dim

// ---- scratch (device globals; no allocations allowed) ----
__device__ __align__(16) float g_base[NN][DIM];
__device__ __align__(16) float g_bvec[NG][NN][DIM];
__device__ int   g_parent[NG][NN];
__device__ int   g_ccount[NG][NN];
__device__ int   g_onpath[NG][NN];
__device__ int   g_path[NG][NN];
__device__ int   g_plen[NG];
__device__ int   g_edges_eff[NN];
__device__ int   g_pathdone[NG];
__device__ float g_dscore;

// ---- acquire/release primitives (cross-block seam only) ----
__device__ __forceinline__ int ld_acquire(const int* p) {
    int v;
    asm volatile("ld.acquire.gpu.global.u32 %0, [%1];" : "=r"(v) : "l"(p) : "memory");
    return v;
}
__device__ __forceinline__ void red_release_add(int* p, int v) {
    asm volatile("red.release.gpu.global.add.u32 [%0], %1;" :: "l"(p), "r"(v) : "memory");
}
__device__ __forceinline__ void wait_ge(const int* p, int need) {
    while (ld_acquire(p) < need) { }
    __syncwarp();
}

// ---------------------------------------------------------------------------
// Streaming matvec over K rows: thread owns 4 output dims; W4[k*DIM/4] =
// W[k][d0..d0+3]. CH-deep double buffer -> 2*CH LDG.128 in flight.
// ---------------------------------------------------------------------------
template<int K, int CH>
__device__ __forceinline__ void mv_stream(const float4* __restrict__ W4,
                                          const float* __restrict__ r,
                                          float4& m) {
    constexpr int STEP = 2 * CH;
    constexpr int NCH  = (K + STEP - 1) / STEP;
    float4 A[CH], B[CH];
#pragma unroll
    for (int i = 0; i < CH; ++i)
        A[i] = (i < K) ? W4[i * (DIM / 4)] : make_float4(0.f, 0.f, 0.f, 0.f);
#pragma unroll
    for (int o = 0; o < NCH; ++o) {
        const int kb = o * STEP, k2 = kb + CH, k3 = kb + STEP;
#pragma unroll
        for (int i = 0; i < CH; ++i)
            B[i] = (k2 + i < K) ? W4[(k2 + i) * (DIM / 4)] : make_float4(0.f, 0.f, 0.f, 0.f);
#pragma unroll
        for (int i = 0; i < CH; ++i)
            if (kb + i < K) {
                const float rk = r[kb + i];
                m.x += rk * A[i].x; m.y += rk * A[i].y;
                m.z += rk * A[i].z; m.w += rk * A[i].w;
            }
#pragma unroll
        for (int i = 0; i < CH; ++i)
            A[i] = (k3 + i < K) ? W4[(k3 + i) * (DIM / 4)] : make_float4(0.f, 0.f, 0.f, 0.f);
#pragma unroll
        for (int i = 0; i < CH; ++i)
            if (k2 + i < K) {
                const float rk = r[k2 + i];
                m.x += rk * B[i].x; m.y += rk * B[i].y;
                m.z += rk * B[i].z; m.w += rk * B[i].w;
            }
    }
}

__device__ __forceinline__ float warp_sum(float s) {
#pragma unroll
    for (int o = 16; o; o >>= 1) s += __shfl_down_sync(0xffffffffu, s, o);
    return s;
}
__device__ __forceinline__ float4 relu4(float4 v) {
    return make_float4(fmaxf(v.x, 0.f), fmaxf(v.y, 0.f), fmaxf(v.z, 0.f), fmaxf(v.w, 0.f));
}
// Single-warp L1 prefetch of one 64KB matrix (16 lines per lane).
__device__ __forceinline__ void prefetch_l1_full(const char* base, int c) {
#pragma unroll
    for (int i = 0; i < 16; ++i)
        asm volatile("prefetch.global.L1 [%0];" :: "l"(base + ((c + (i << 5)) << 7)));
}
// Cooperative 8-warp L1 prefetch (2 lines per lane).
__device__ __forceinline__ void prefetch_l1_slice(const char* base, int w, int c) {
    const char* p = base + (((w << 6) + c) << 7);
    asm volatile("prefetch.global.L1 [%0];" :: "l"(p));
    asm volatile("prefetch.global.L1 [%0];" :: "l"(p + (32 << 7)));
}

// ---------------------------------------------------------------------------
// Base/structure kernel. Blocks 0..7: per-graph structure (counts, parents,
// onpath flags, pos->root path) + flag reset. Blocks 8..135: one node each,
// base[n] = vecs[data[n]] @ dW + db via 4-warp k-split; pos block adds
// d_score = sbias + base[pos] . sdw.
// ---------------------------------------------------------------------------
__global__ __launch_bounds__(128, 1) void k_base(
        const int* __restrict__ graphs, const int* __restrict__ edges,
        const int* __restrict__ posp,   const int* __restrict__ data,
        const float* __restrict__ vecs, const float* __restrict__ dW,
        const float* __restrict__ db,   const float* __restrict__ sdw,
        const float* __restrict__ sbias) {
    const int t = threadIdx.x;
    const int pos = posp[0];
    if (blockIdx.x < NG) {
        const int g = blockIdx.x;
        g_ccount[g][t] = 0;
        g_onpath[g][t] = 0;
        if (g == 0) g_edges_eff[t] = (t == pos) ? -1 : edges[t];
        if (t == 0) g_pathdone[g] = 0;
        __syncthreads();
        const int off = graphs[g * NN + t];
        const int par = (off == 0) ? -1 : (t + off);
        g_parent[g][t] = par;
        if (par >= 0) atomicAdd(&g_ccount[g][par], 1);
        if (t == 0) {
            int cur = pos, len = 0;
            while (len < NN) {
                g_path[g][len++] = cur;
                g_onpath[g][cur] = 1;
                const int o = graphs[g * NN + cur];
                if (o == 0) break;
                cur += o;
            }
            g_plen[g] = len;
        }
    } else {
        __shared__ __align__(16) float shv[304];
        __shared__ __align__(16) float part[4][DIM];
        const int n = blockIdx.x - NG;
        const int w = t >> 5, c = t & 31, d0 = c * 4;
        const float* vr = vecs + (long long)data[n] * VEC;
        for (int i = t; i < 304; i += 128) shv[i] = (i < VEC) ? vr[i] : 0.f;
        __syncthreads();
        const int k0 = w * 75;                 // 4 * 75 = 300 exact
        float4 acc = make_float4(0.f, 0.f, 0.f, 0.f);
        mv_stream<75, 8>((const float4*)(dW + (long long)k0 * DIM + d0), shv + k0, acc);
        *(float4*)&part[w][d0] = acc;
        __syncthreads();
        if (w == 0) {
            float4 m = *(const float4*)(db + d0);
#pragma unroll
            for (int ww = 0; ww < 4; ++ww) {
                const float4 p = *(const float4*)&part[ww][d0];
                m.x += p.x; m.y += p.y; m.z += p.z; m.w += p.w;
            }
            *(float4*)&g_base[n][d0] = m;
            if (n == pos) {
                const float4 s4 = *(const float4*)(sdw + d0);
                const float s = warp_sum(m.x * s4.x + m.y * s4.y + m.z * s4.z + m.w * s4.w);
                if (c == 0) g_dscore = sbias[0] + s;
            }
        }
    }
}

// ---------------------------------------------------------------------------
// Main kernel: 136 blocks x 256 threads (1/SM, all resident).
// Blocks 0..7 (TREE, graph g = b): the whole tree recursion runs inside the
//   block. vacc lives in 64KB dynamic smem, done-counters in smem -> a hop's
//   handshake is LDS-spin + membar.cta instead of L2 round trips. Warp w owns
//   nodes n = w + 8i in increasing order (children have smaller indices ->
//   schedule is deadlock-free by induction on node index). Non-path node:
//   relu (if internal), warp matvec W[edge[n]], shared atomicAdd into parent
//   vacc, fence, bump parent counter. Path node: store bvec to GLOBAL and
//   red.release g_pathdone[g] (per-node release makes every bvec visible to
//   any acquirer that reads pathdone == plen).
// Blocks 8..135 (MATRIX): b2 = b-8, g = b2>>4, row e = (b2&15)*8 + w. Wait
//   pathdone == plen, then walk the pos->root chain of matvecs for row e
//   exactly as the proven round-7 phase 2 (coop L1 prefetch of shared steps).
// ---------------------------------------------------------------------------
__global__ __launch_bounds__(256, 1) void k_main(
        const float* __restrict__ ew,  const float* __restrict__ ebias,
        const float* __restrict__ sew, float* __restrict__ out) {
    extern __shared__ __align__(16) float svacc[];        // [NN][DIM] (64KB)
    __shared__ int scdone[NN];
    __shared__ int sccount[NN], sparent[NN], seid[NN], sonpath[NN];
    __shared__ __align__(16) float sr[8][DIM];
    const int t = threadIdx.x, w = t >> 5, c = t & 31;
    const int d0 = c * 4;
    const int b = blockIdx.x;

    if (b < NG) {
        // ===================== TREE block (graph g = b) ====================
        const int g = b;
        if (t < NN) {
            sccount[t] = g_ccount[g][t];
            sparent[t] = g_parent[g][t];
            sonpath[t] = g_onpath[g][t];
            seid[t]    = g_edges_eff[t];
            scdone[t]  = 0;
        }
        {   // vacc := base (linear copy, layouts match)
            float4* sv4 = (float4*)svacc;
            const float4* b4 = (const float4*)g_base;
            for (int i = t; i < NN * DIM / 4; i += 256) sv4[i] = b4[i];
        }
        __syncthreads();

#pragma unroll 1
        for (int i = 0; i < NN / 8; ++i) {
            const int n    = w + 8 * i;        // increasing per warp
            const int need = sccount[n];
            const int par  = sparent[n];
            const int eid  = seid[n];
            if (eid >= 0 && need > 0)          // warm L1 while waiting
                prefetch_l1_full((const char*)(ew + (long long)eid * DIM * DIM), c);
            if (need > 0) {
                volatile int* f = &scdone[n];
                while (*f < need) { }
                __threadfence_block();
            }
            float4 v = *(const float4*)&svacc[n * DIM + d0];
            if (sonpath[n]) {
                *(float4*)&g_bvec[g][n][d0] = v;        // raw; relu by consumer
                __syncwarp();
                if (c == 0) {
                    red_release_add(&g_pathdone[g], 1); // orders the bvec store
                    if (par >= 0) atomicAdd(&scdone[par], 1);
                }
            } else {
                if (need > 0) v = relu4(v);             // relu iff internal
                *(float4*)&sr[w][d0] = v;
                __syncwarp();
                float4 m = *(const float4*)(ebias + eid * DIM + d0);
                mv_stream<DIM, 16>((const float4*)(ew + (long long)eid * DIM * DIM + d0),
                                   sr[w], m);
                float* dst = &svacc[par * DIM + d0];
                atomicAdd(dst + 0, m.x); atomicAdd(dst + 1, m.y);
                atomicAdd(dst + 2, m.z); atomicAdd(dst + 3, m.w);
                __threadfence_block();
                __syncwarp();
                if (c == 0) atomicAdd(&scdone[par], 1);
            }
            __syncwarp();
        }
    } else {
        // ===================== MATRIX block ================================
        const int b2 = b - NG;
        const int g  = b2 >> 4;
        const int e  = (b2 & 15) * 8 + w;
        {   // warm L2 with this row's step-0 weights while waiting
            const char* wb = (const char*)(ew + (long long)e * DIM * DIM);
#pragma unroll
            for (int i = 0; i < 16; ++i)
                asm volatile("prefetch.global.L2 [%0];" :: "l"(wb + ((c + (i << 5)) << 7)));
        }
        const int plen = g_plen[g];            // written by k_base (prev launch)
        wait_ge(&g_pathdone[g], plen);

        const int p0 = g_path[g][0];
        float4 r0 = __ldcg((const float4*)&g_bvec[g][p0][d0]);
        if (g_ccount[g][p0] > 0) r0 = relu4(r0);
        *(float4*)&sr[w][d0] = r0;
        __syncwarp();

        // step 0: per-row weight matrix W[e]; prefetch step-1 shared W to L1
        if (plen > 1)
            prefetch_l1_slice((const char*)(ew +
                (long long)g_edges_eff[g_path[g][1]] * DIM * DIM), w, c);
        float4 m = *(const float4*)(ebias + e * DIM + d0);
        mv_stream<DIM, 16>((const float4*)(ew + (long long)e * DIM * DIM + d0), sr[w], m);

        // steps 1..plen-1: shared weight matrix per (graph, step)
        for (int s = 1; s < plen; ++s) {
            const int a = g_path[g][s];
            const float4 bv = __ldcg((const float4*)&g_bvec[g][a][d0]);
            const float4 r = make_float4(fmaxf(bv.x + m.x, 0.f), fmaxf(bv.y + m.y, 0.f),
                                         fmaxf(bv.z + m.z, 0.f), fmaxf(bv.w + m.w, 0.f));
            __syncwarp();                      // all lanes done reading prior sr
            *(float4*)&sr[w][d0] = r;
            __syncwarp();
            const int eid = g_edges_eff[a];
            if (s + 1 < plen)                  // prefetch next step's shared W
                prefetch_l1_slice((const char*)(ew +
                    (long long)g_edges_eff[g_path[g][s + 1]] * DIM * DIM), w, c);
            m = *(const float4*)(ebias + eid * DIM + d0);
            mv_stream<DIM, 16>((const float4*)(ew + (long long)eid * DIM * DIM + d0),
                               sr[w], m);
        }

        const float4 s4 = *(const float4*)(sew + d0);
        const float s = warp_sum(m.x * s4.x + m.y * s4.y + m.z * s4.z + m.w * s4.w);
        if (c == 0) out[g * NE + e] = __ldcg(&g_dscore) + s;
    }
}

extern "C" void kernel_launch(void* const* d_in, const int* in_sizes, int n_in,
                              void* d_out, int out_size) {
    const int*   data   = (const int*)d_in[0];
    // d_in[1] = types (unused: single data_type)
    const int*   graphs = (const int*)d_in[2];
    const int*   edges  = (const int*)d_in[3];
    const int*   posp   = (const int*)d_in[4];
    const float* vecs   = (const float*)d_in[5];
    const float* dW     = (const float*)d_in[6];
    const float* db     = (const float*)d_in[7];
    const float* ew     = (const float*)d_in[8];
    const float* ebias  = (const float*)d_in[9];
    const float* sew    = (const float*)d_in[10];
    const float* sdw    = (const float*)d_in[11];
    const float* sbias  = (const float*)d_in[12];
    float* out = (float*)d_out;

    const int dyn = NN * DIM * (int)sizeof(float);          // 64KB vacc
    static int smem_set = 0;
    if (!smem_set) {
        cudaFuncSetAttribute(k_main, cudaFuncAttributeMaxDynamicSharedMemorySize, dyn);
        smem_set = 1;
    }
    k_base<<<NG + NN, 128>>>(graphs, edges, posp, data, vecs, dW, db, sdw, sbias);
    k_main<<<NG + NN, 256, dyn>>>(ew, ebias, sew, out);
}

// round 10
// speedup vs baseline: 1.1815x; 1.1815x over previous
#include <cuda_runtime.h>

#define NG  8     // graphs
#define NN  128   // nodes
#define DIM 128   // embedding dim
#define NE  128   // edge types
#define VEC 300   // word-vec dim

// ---- scratch (device globals; no allocations allowed) ----
__device__ __align__(16) float g_base[NN][DIM];
__device__ __align__(16) float g_vacc[NG][NN][DIM];
__device__ __align__(16) float g_bvec[NG][NN][DIM];
__device__ int   g_parent[NG][NN];
__device__ int   g_ccount[NG][NN];
__device__ int   g_cdone[NG][NN];
__device__ int   g_onpath[NG][NN];
__device__ int   g_path[NG][NN];
__device__ int   g_plen[NG];
__device__ int   g_edges_eff[NN];
__device__ int   g_pathdone[NG];
__device__ float g_dscore;

// ---- acquire/release primitives ----
__device__ __forceinline__ int ld_acquire(const int* p) {
    int v;
    asm volatile("ld.acquire.gpu.global.u32 %0, [%1];" : "=r"(v) : "l"(p) : "memory");
    return v;
}
__device__ __forceinline__ void red_release_add(int* p, int v) {
    asm volatile("red.release.gpu.global.add.u32 [%0], %1;" :: "l"(p), "r"(v) : "memory");
}
// ALL lanes spin: every lane carries its own acquire edge.
__device__ __forceinline__ void wait_ge(const int* p, int need) {
    while (ld_acquire(p) < need) { }
    __syncwarp();
}
#define BARP(id) asm volatile("bar.sync %0, 64;" :: "r"(id) : "memory")

// ---------------------------------------------------------------------------
// float4 streaming matvec (k_base only): thread owns 4 output dims.
// ---------------------------------------------------------------------------
template<int K, int CH>
__device__ __forceinline__ void mv_stream(const float4* __restrict__ W4,
                                          const float* __restrict__ r,
                                          float4& m) {
    constexpr int STEP = 2 * CH;
    constexpr int NCH  = (K + STEP - 1) / STEP;
    float4 A[CH], B[CH];
#pragma unroll
    for (int i = 0; i < CH; ++i)
        A[i] = (i < K) ? W4[i * (DIM / 4)] : make_float4(0.f, 0.f, 0.f, 0.f);
#pragma unroll
    for (int o = 0; o < NCH; ++o) {
        const int kb = o * STEP, k2 = kb + CH, k3 = kb + STEP;
#pragma unroll
        for (int i = 0; i < CH; ++i)
            B[i] = (k2 + i < K) ? W4[(k2 + i) * (DIM / 4)] : make_float4(0.f, 0.f, 0.f, 0.f);
#pragma unroll
        for (int i = 0; i < CH; ++i)
            if (kb + i < K) {
                const float rk = r[kb + i];
                m.x += rk * A[i].x; m.y += rk * A[i].y;
                m.z += rk * A[i].z; m.w += rk * A[i].w;
            }
#pragma unroll
        for (int i = 0; i < CH; ++i)
            A[i] = (k3 + i < K) ? W4[(k3 + i) * (DIM / 4)] : make_float4(0.f, 0.f, 0.f, 0.f);
#pragma unroll
        for (int i = 0; i < CH; ++i)
            if (k2 + i < K) {
                const float rk = r[k2 + i];
                m.x += rk * B[i].x; m.y += rk * B[i].y;
                m.z += rk * B[i].z; m.w += rk * B[i].w;
            }
    }
}

// ---------------------------------------------------------------------------
// float2 streaming half-matvec (k_main): thread owns 2 output dims in the
// warp's 64-dim d-half; full K range. CH float2 double-buffer -> 2*CH LDG.64
// in flight (CH=16 -> 32, under the ~55/warp LSU cap).
// ---------------------------------------------------------------------------
template<int K, int CH>
__device__ __forceinline__ void mv_stream2(const float2* __restrict__ W2,
                                           const float* __restrict__ r,
                                           float2& m) {
    constexpr int STEP = 2 * CH;
    constexpr int NCH  = (K + STEP - 1) / STEP;
    float2 A[CH], B[CH];
#pragma unroll
    for (int i = 0; i < CH; ++i)
        A[i] = (i < K) ? W2[i * (DIM / 2)] : make_float2(0.f, 0.f);
#pragma unroll
    for (int o = 0; o < NCH; ++o) {
        const int kb = o * STEP, k2 = kb + CH, k3 = kb + STEP;
#pragma unroll
        for (int i = 0; i < CH; ++i)
            B[i] = (k2 + i < K) ? W2[(k2 + i) * (DIM / 2)] : make_float2(0.f, 0.f);
#pragma unroll
        for (int i = 0; i < CH; ++i)
            if (kb + i < K) {
                const float rk = r[kb + i];
                m.x += rk * A[i].x; m.y += rk * A[i].y;
            }
#pragma unroll
        for (int i = 0; i < CH; ++i)
            A[i] = (k3 + i < K) ? W2[(k3 + i) * (DIM / 2)] : make_float2(0.f, 0.f);
#pragma unroll
        for (int i = 0; i < CH; ++i)
            if (k2 + i < K) {
                const float rk = r[k2 + i];
                m.x += rk * B[i].x; m.y += rk * B[i].y;
            }
    }
}

__device__ __forceinline__ float warp_sum(float s) {
#pragma unroll
    for (int o = 16; o; o >>= 1) s += __shfl_down_sync(0xffffffffu, s, o);
    return s;
}
// Prefetch this warp's 32KB d-half of a 64KB W matrix into L1 (8 lines/lane):
// for k rows c, c+32, c+64, c+96: 2 lines at k*512 + h*256.
__device__ __forceinline__ void prefetch_half(const char* Wb, int h, int c) {
#pragma unroll
    for (int i = 0; i < 4; ++i) {
        const char* p = Wb + ((c + (i << 5)) << 9) + (h << 8);
        asm volatile("prefetch.global.L1 [%0];" :: "l"(p));
        asm volatile("prefetch.global.L1 [%0];" :: "l"(p + 128));
    }
}

// ---------------------------------------------------------------------------
// Base/structure kernel. Blocks 0..7: per-graph structure (counts, parents,
// onpath flags, pos->root path) + flag reset. Blocks 8..135: one node each,
// base[n] = vecs[data[n]] @ dW + db (4-warp k-split); pos block adds d_score.
// All blocks help zero g_vacc.
// ---------------------------------------------------------------------------
__global__ __launch_bounds__(128, 1) void k_base(
        const int* __restrict__ graphs, const int* __restrict__ edges,
        const int* __restrict__ posp,   const int* __restrict__ data,
        const float* __restrict__ vecs, const float* __restrict__ dW,
        const float* __restrict__ db,   const float* __restrict__ sdw,
        const float* __restrict__ sbias) {
    const int t = threadIdx.x;
    const int pos = posp[0];
    {   // cooperative zero of g_vacc (512KB)
        float4* v4 = (float4*)g_vacc;
        const int total = NG * NN * DIM / 4;
        for (int i = blockIdx.x * 128 + t; i < total; i += (NG + NN) * 128)
            v4[i] = make_float4(0.f, 0.f, 0.f, 0.f);
    }
    if (blockIdx.x < NG) {
        const int g = blockIdx.x;
        g_ccount[g][t] = 0;
        g_cdone[g][t]  = 0;
        g_onpath[g][t] = 0;
        if (g == 0) g_edges_eff[t] = (t == pos) ? -1 : edges[t];
        if (t == 0) g_pathdone[g] = 0;
        __syncthreads();
        const int off = graphs[g * NN + t];
        const int par = (off == 0) ? -1 : (t + off);
        g_parent[g][t] = par;
        if (par >= 0) atomicAdd(&g_ccount[g][par], 1);
        if (t == 0) {
            int cur = pos, len = 0;
            while (len < NN) {
                g_path[g][len++] = cur;
                g_onpath[g][cur] = 1;
                const int o = graphs[g * NN + cur];
                if (o == 0) break;
                cur += o;
            }
            g_plen[g] = len;
        }
    } else {
        __shared__ __align__(16) float shv[304];
        __shared__ __align__(16) float part[4][DIM];
        const int n = blockIdx.x - NG;
        const int w = t >> 5, c = t & 31, d0 = c * 4;
        const float* vr = vecs + (long long)data[n] * VEC;
        for (int i = t; i < 304; i += 128) shv[i] = (i < VEC) ? vr[i] : 0.f;
        __syncthreads();
        const int k0 = w * 75;                 // 4 * 75 = 300 exact
        float4 acc = make_float4(0.f, 0.f, 0.f, 0.f);
        mv_stream<75, 8>((const float4*)(dW + (long long)k0 * DIM + d0), shv + k0, acc);
        *(float4*)&part[w][d0] = acc;
        __syncthreads();
        if (w == 0) {
            float4 m = *(const float4*)(db + d0);
#pragma unroll
            for (int ww = 0; ww < 4; ++ww) {
                const float4 p = *(const float4*)&part[ww][d0];
                m.x += p.x; m.y += p.y; m.z += p.z; m.w += p.w;
            }
            *(float4*)&g_base[n][d0] = m;
            if (n == pos) {
                const float4 s4 = *(const float4*)(sdw + d0);
                const float s = warp_sum(m.x * s4.x + m.y * s4.y + m.z * s4.z + m.w * s4.w);
                if (c == 0) g_dscore = sbias[0] + s;
            }
        }
    }
}

// ---------------------------------------------------------------------------
// Main kernel: 128 blocks x 512 threads (16 warps), 1 block/SM, all resident.
// Warp-pair (w, w+8) is the unit: pr = w&7 (pair id), h = w>>3 (d-half).
// Phase 1 (tree): pair pr of block n owns task (n, g=pr). Counters count
//   WARP arrivals (2 per child). Each warp: prefetch its W d-half, wait
//   2*ccount, read its base+vacc half, then: path node -> store bvec half,
//   release-bump pathdone and parent counter; else relu (if internal), stage
//   r-half in shared, pair barrier, d-half matvec (full K, own 64 out dims),
//   atomicAdd own half into parent vacc, release-bump parent counter.
// Phase 2 (matrix, overlapped): pair pr of block b walks row e=(b&15)*8+pr of
//   graph g=b>>4. Step s is gated on pathdone >= 2(s+1) — path nodes finish
//   in order, so the chain tracks the tree climb; only the post-root step is
//   exposed. Each warp computes its m-half; halves exchange via shared.
// ---------------------------------------------------------------------------
__global__ __launch_bounds__(512, 1) void k_main(
        const float* __restrict__ ew,  const float* __restrict__ ebias,
        const float* __restrict__ sew, float* __restrict__ out) {
    __shared__ __align__(16) float shr1[8][DIM];   // phase-1 r per pair
    __shared__ __align__(16) float shr2[8][DIM];   // phase-2 r per pair
    __shared__ float sdot[8];
    const int t = threadIdx.x, w = t >> 5, c = t & 31;
    const int pr = w & 7, h = w >> 3;
    const int bid = 1 + pr;                        // named barrier per pair
    const int dh = 64 * h + 2 * c;                 // this warp's 2 dims
    const int b = blockIdx.x;

    // ================= phase 1: tree task (n = block, g = pr) ==============
    {
        const int n = b;
        const int g = pr;
        const int need2  = 2 * g_ccount[g][n];
        const int par    = g_parent[g][n];
        const int onpath = g_onpath[g][n];
        const int eid    = g_edges_eff[n];
        if (!onpath)   // warm L1 with this warp's W d-half while waiting
            prefetch_half((const char*)(ew + (long long)eid * DIM * DIM), h, c);
        if (need2 > 0) wait_ge(&g_cdone[g][n], need2);
        float2 v = *(const float2*)&g_base[n][dh];
        if (need2 > 0) {
            const float2 va = __ldcg((const float2*)&g_vacc[g][n][dh]);
            v.x += va.x; v.y += va.y;
        }
        if (onpath) {
            *(float2*)&g_bvec[g][n][dh] = v;
            __syncwarp();
            if (c == 0) {
                red_release_add(&g_pathdone[g], 1);        // orders own bvec half
                if (par >= 0) red_release_add(&g_cdone[g][par], 1);
            }
        } else {
            if (need2 > 0) { v.x = fmaxf(v.x, 0.f); v.y = fmaxf(v.y, 0.f); }
            shr1[pr][dh] = v.x; shr1[pr][dh + 1] = v.y;
            BARP(bid);                                     // full r assembled
            float2 m = *(const float2*)(ebias + eid * DIM + dh);
            mv_stream2<DIM, 16>((const float2*)(ew + (long long)eid * DIM * DIM + dh),
                                shr1[pr], m);
            atomicAdd(&g_vacc[g][par][dh],     m.x);
            atomicAdd(&g_vacc[g][par][dh + 1], m.y);
            __syncwarp();
            if (c == 0) red_release_add(&g_cdone[g][par], 1);
        }
        __syncwarp();
    }

    // ================= phase 2: matrix chain (g = b>>4, row e) =============
    {
        const int g = b >> 4;
        const int e = (b & 15) * 8 + pr;
        {   // warm L2 with this warp's half of the step-0 weights
            const char* wb = (const char*)(ew + (long long)e * DIM * DIM);
#pragma unroll
            for (int i = 0; i < 4; ++i) {
                const char* p = wb + ((c + (i << 5)) << 9) + (h << 8);
                asm volatile("prefetch.global.L2 [%0];" :: "l"(p));
                asm volatile("prefetch.global.L2 [%0];" :: "l"(p + 128));
            }
        }
        const int plen = g_plen[g];
        wait_ge(&g_pathdone[g], 2);            // v(pos) ready (both halves)

        const int p0 = g_path[g][0];
        float2 r0 = __ldcg((const float2*)&g_bvec[g][p0][dh]);
        if (g_ccount[g][p0] > 0) { r0.x = fmaxf(r0.x, 0.f); r0.y = fmaxf(r0.y, 0.f); }
        shr2[pr][dh] = r0.x; shr2[pr][dh + 1] = r0.y;
        BARP(bid);

        // step 0: per-row weight matrix W[e], own d-half
        float2 m = *(const float2*)(ebias + e * DIM + dh);
        mv_stream2<DIM, 16>((const float2*)(ew + (long long)e * DIM * DIM + dh),
                            shr2[pr], m);

        // steps 1..plen-1, each gated on its path node's completion
        for (int s = 1; s < plen; ++s) {
            const int a = g_path[g][s];
            wait_ge(&g_pathdone[g], 2 * (s + 1));
            const int eid = g_edges_eff[a];
            prefetch_half((const char*)(ew + (long long)eid * DIM * DIM), h, c);
            const float2 bv = __ldcg((const float2*)&g_bvec[g][a][dh]);
            const float2 r = make_float2(fmaxf(bv.x + m.x, 0.f), fmaxf(bv.y + m.y, 0.f));
            BARP(bid);                         // both warps done reading prior shr2
            shr2[pr][dh] = r.x; shr2[pr][dh + 1] = r.y;
            BARP(bid);
            m = *(const float2*)(ebias + eid * DIM + dh);
            mv_stream2<DIM, 16>((const float2*)(ew + (long long)eid * DIM * DIM + dh),
                                shr2[pr], m);
        }

        // score: d_score + m . sew (halves combined via shared)
        const float2 s2 = *(const float2*)(sew + dh);
        const float part = warp_sum(m.x * s2.x + m.y * s2.y);
        if (h == 1 && c == 0) sdot[pr] = part;
        BARP(bid);
        if (h == 0 && c == 0) out[g * NE + e] = g_dscore + part + sdot[pr];
    }
}

extern "C" void kernel_launch(void* const* d_in, const int* in_sizes, int n_in,
                              void* d_out, int out_size) {
    const int*   data   = (const int*)d_in[0];
    // d_in[1] = types (unused: single data_type)
    const int*   graphs = (const int*)d_in[2];
    const int*   edges  = (const int*)d_in[3];
    const int*   posp   = (const int*)d_in[4];
    const float* vecs   = (const float*)d_in[5];
    const float* dW     = (const float*)d_in[6];
    const float* db     = (const float*)d_in[7];
    const float* ew     = (const float*)d_in[8];
    const float* ebias  = (const float*)d_in[9];
    const float* sew    = (const float*)d_in[10];
    const float* sdw    = (const float*)d_in[11];
    const float* sbias  = (const float*)d_in[12];
    float* out = (float*)d_out;

    k_base<<<NG + NN, 128>>>(graphs, edges, posp, data, vecs, dW, db, sdw, sbias);
    k_main<<<NN, 512>>>(ew, ebias, sew, out);
}

// round 11
// speedup vs baseline: 1.4759x; 1.2491x over previous
#include <cuda_runtime.h>

#define NG  8     // graphs
#define NN  128   // nodes
#define DIM 128   // embedding dim
#define NE  128   // edge types
#define VEC 300   // word-vec dim

// ---- scratch (device globals; no allocations allowed) ----
__device__ __align__(16) float g_vacc[NG][NN][DIM];   // seeded with base[n]
__device__ __align__(16) float g_bvec[NG][NN][DIM];
__device__ __align__(16) int4 g_meta[NG][NN];  // x=parent y=ccount z=onpath w=eid
__device__ int   g_cdone[NG][NN];
__device__ int   g_path[NG][NN];
__device__ int   g_plen[NG];
__device__ int   g_pathdone[NG];
__device__ float g_dscore;

// ---- acquire/release primitives ----
__device__ __forceinline__ int ld_acquire(const int* p) {
    int v;
    asm volatile("ld.acquire.gpu.global.u32 %0, [%1];" : "=r"(v) : "l"(p) : "memory");
    return v;
}
__device__ __forceinline__ void red_release_add(int* p, int v) {
    asm volatile("red.release.gpu.global.add.u32 [%0], %1;" :: "l"(p), "r"(v) : "memory");
}
__device__ __forceinline__ int atom_acqrel_add(int* p, int v) {
    int old;
    asm volatile("atom.acq_rel.gpu.global.add.u32 %0, [%1], %2;"
                 : "=r"(old) : "l"(p), "r"(v) : "memory");
    return old;
}
// Phase-2 gating only (off critical path while tree runs): backoff poll.
__device__ __forceinline__ void wait_ge(const int* p, int need) {
    while (ld_acquire(p) < need) { __nanosleep(64); }
    __syncwarp();
}
// lane0 bumps the arrival counter; old value broadcast to the warp.
__device__ __forceinline__ int bump_arrive(int* ctr, int c) {
    int old = 0;
    if (c == 0) old = atom_acqrel_add(ctr, 1);
    old = __shfl_sync(0xffffffffu, old, 0);
    return old;
}

// ---------------------------------------------------------------------------
// Streaming matvec: thread owns 4 output dims; W4[k*DIM/4] = W[k][d0..d0+3].
// CH-deep double buffer -> 2*CH LDG.128 in flight (needs big reg budget).
// ---------------------------------------------------------------------------
template<int K, int CH>
__device__ __forceinline__ void mv_stream(const float4* __restrict__ W4,
                                          const float* __restrict__ r,
                                          float4& m) {
    constexpr int STEP = 2 * CH;
    constexpr int NCH  = (K + STEP - 1) / STEP;
    float4 A[CH], B[CH];
#pragma unroll
    for (int i = 0; i < CH; ++i)
        A[i] = (i < K) ? W4[i * (DIM / 4)] : make_float4(0.f, 0.f, 0.f, 0.f);
#pragma unroll
    for (int o = 0; o < NCH; ++o) {
        const int kb = o * STEP, k2 = kb + CH, k3 = kb + STEP;
#pragma unroll
        for (int i = 0; i < CH; ++i)
            B[i] = (k2 + i < K) ? W4[(k2 + i) * (DIM / 4)] : make_float4(0.f, 0.f, 0.f, 0.f);
#pragma unroll
        for (int i = 0; i < CH; ++i)
            if (kb + i < K) {
                const float rk = r[kb + i];
                m.x += rk * A[i].x; m.y += rk * A[i].y;
                m.z += rk * A[i].z; m.w += rk * A[i].w;
            }
#pragma unroll
        for (int i = 0; i < CH; ++i)
            A[i] = (k3 + i < K) ? W4[(k3 + i) * (DIM / 4)] : make_float4(0.f, 0.f, 0.f, 0.f);
#pragma unroll
        for (int i = 0; i < CH; ++i)
            if (k2 + i < K) {
                const float rk = r[k2 + i];
                m.x += rk * B[i].x; m.y += rk * B[i].y;
                m.z += rk * B[i].z; m.w += rk * B[i].w;
            }
    }
}

__device__ __forceinline__ float warp_sum(float s) {
#pragma unroll
    for (int o = 16; o; o >>= 1) s += __shfl_down_sync(0xffffffffu, s, o);
    return s;
}
__device__ __forceinline__ float4 relu4(float4 v) {
    return make_float4(fmaxf(v.x, 0.f), fmaxf(v.y, 0.f), fmaxf(v.z, 0.f), fmaxf(v.w, 0.f));
}
// Single-warp L2 prefetch of a 64KB matrix (16 lines/lane) — used to warm the
// NEXT hop's weights while the current matvec runs.
__device__ __forceinline__ void prefetch_l2_full(const char* base, int c) {
#pragma unroll
    for (int i = 0; i < 16; ++i)
        asm volatile("prefetch.global.L2 [%0];" :: "l"(base + ((c + (i << 5)) << 7)));
}
// Cooperative 8-warp L1 prefetch (2 lines per lane) — phase-2 shared steps.
__device__ __forceinline__ void prefetch_l1_slice(const char* base, int w, int c) {
    const char* p = base + (((w << 6) + c) << 7);
    asm volatile("prefetch.global.L1 [%0];" :: "l"(p));
    asm volatile("prefetch.global.L1 [%0];" :: "l"(p + (32 << 7)));
}

// ---------------------------------------------------------------------------
// Base/structure kernel. Blocks 0..7: per-graph structure -> packed g_meta
// (parent, ccount, onpath, eid), path arrays, counter resets. Blocks 8..135:
// node n = b-8: base[n] = vecs[data[n]] @ dW + db (4-warp k-split), then
// SEED g_vacc[g][n] = base[n] for all 8 graphs. pos block adds d_score.
// ---------------------------------------------------------------------------
__global__ __launch_bounds__(128, 1) void k_base(
        const int* __restrict__ graphs, const int* __restrict__ edges,
        const int* __restrict__ posp,   const int* __restrict__ data,
        const float* __restrict__ vecs, const float* __restrict__ dW,
        const float* __restrict__ db,   const float* __restrict__ sdw,
        const float* __restrict__ sbias) {
    const int t = threadIdx.x;
    const int pos = posp[0];
    if (blockIdx.x < NG) {
        const int g = blockIdx.x;
        __shared__ int s_cc[NN], s_op[NN];
        s_cc[t] = 0; s_op[t] = 0;
        g_cdone[g][t] = 0;
        if (t == 0) g_pathdone[g] = 0;
        __syncthreads();
        const int off = graphs[g * NN + t];
        const int par = (off == 0) ? -1 : (t + off);
        if (par >= 0) atomicAdd(&s_cc[par], 1);
        if (t == 0) {
            int cur = pos, len = 0;
            while (len < NN) {
                g_path[g][len++] = cur;
                s_op[cur] = 1;
                const int o = graphs[g * NN + cur];
                if (o == 0) break;
                cur += o;
            }
            g_plen[g] = len;
        }
        __syncthreads();
        const int eid = (t == pos) ? -1 : edges[t];
        g_meta[g][t] = make_int4(par, s_cc[t], s_op[t], eid);
    } else {
        __shared__ __align__(16) float shv[304];
        __shared__ __align__(16) float part[4][DIM];
        __shared__ __align__(16) float sh_base[DIM];
        const int n = blockIdx.x - NG;
        const int w = t >> 5, c = t & 31, d0 = c * 4;
        const float* vr = vecs + (long long)data[n] * VEC;
        for (int i = t; i < 304; i += 128) shv[i] = (i < VEC) ? vr[i] : 0.f;
        __syncthreads();
        const int k0 = w * 75;                 // 4 * 75 = 300 exact
        float4 acc = make_float4(0.f, 0.f, 0.f, 0.f);
        mv_stream<75, 8>((const float4*)(dW + (long long)k0 * DIM + d0), shv + k0, acc);
        *(float4*)&part[w][d0] = acc;
        __syncthreads();
        if (w == 0) {
            float4 m = *(const float4*)(db + d0);
#pragma unroll
            for (int ww = 0; ww < 4; ++ww) {
                const float4 p = *(const float4*)&part[ww][d0];
                m.x += p.x; m.y += p.y; m.z += p.z; m.w += p.w;
            }
            *(float4*)&sh_base[d0] = m;
            if (n == pos) {
                const float4 s4 = *(const float4*)(sdw + d0);
                const float s = warp_sum(m.x * s4.x + m.y * s4.y + m.z * s4.z + m.w * s4.w);
                if (c == 0) g_dscore = sbias[0] + s;
            }
        }
        __syncthreads();
        const float4 bb = *(const float4*)&sh_base[d0];
        for (int gg = w; gg < NG; gg += 4)     // seed vacc with base for all graphs
            *(float4*)&g_vacc[gg][n][d0] = bb;
    }
}

// ---------------------------------------------------------------------------
// Main kernel: 128 blocks x 256 threads, 1 block/SM, all resident.
// Phase 1 (chain climb): warp (block=n, g=w) starts ONLY if n is a leaf, then
//   climbs: at node n with value v (registers):
//   - path node: store bvec=v, release-bump pathdone; continue into parent
//     (direct vacc read if parent single-child, else arrival-bump — last
//     arrival continues, others die).
//   - off-path: relu if internal, matvec m = W[eid]^T r + b; if parent
//     single-child: v = vacc[par] + m IN REGISTERS (no handshake!); else
//     REDG m into vacc[par], bump, last arrival reloads and continues.
//   vacc is pre-seeded with base -> no dependency on the parent's own block.
//   No waits anywhere in the climb -> deadlock-free.
// Phase 2 (matrix, overlapped): warp (g=b>>4, row e=(b&15)*8+w) walks the
//   pos->root chain; step s gated on pathdone >= s+1 (path completes in
//   order), so only the post-root step is exposed after the tree finishes.
// ---------------------------------------------------------------------------
__global__ __launch_bounds__(256, 1) void k_main(
        const float* __restrict__ ew,  const float* __restrict__ ebias,
        const float* __restrict__ sew, float* __restrict__ out) {
    __shared__ __align__(16) float shr[8][DIM];
    const int t = threadIdx.x, w = t >> 5, c = t & 31;
    const int d0 = c * 4;
    const int b = blockIdx.x;

    // ================= phase 1: chain climb (start at leaf n=b, g=w) =======
    {
        const int g = w;
        int n = b;
        int4 mt = __ldg((const int4*)&g_meta[g][n]);
        if (mt.y == 0) {                       // leaf: begin climbing
            bool internal = false;
            float4 v = __ldcg((const float4*)&g_vacc[g][n][d0]);   // = base[n]
            while (true) {
                const int par = mt.x, onp = mt.z, eid = mt.w;
                int4 mp = make_int4(-1, 0, 0, -1);
                if (par >= 0) mp = __ldg((const int4*)&g_meta[g][par]);
                if (onp) {
                    *(float4*)&g_bvec[g][n][d0] = v;   // raw; relu by consumer
                    __syncwarp();
                    if (c == 0) red_release_add(&g_pathdone[g], 1);
                    if (par < 0) break;                // root done
                    if (mp.y == 1) {                   // we are the only child
                        v = __ldcg((const float4*)&g_vacc[g][par][d0]);
                    } else {
                        __syncwarp();                  // bvec store ordered above
                        const int old = bump_arrive(&g_cdone[g][par], c);
                        if (old != mp.y - 1) break;    // not last: die
                        __syncwarp();                  // hb: children -> all lanes
                        v = __ldcg((const float4*)&g_vacc[g][par][d0]);
                    }
                } else {
                    const float4 r = internal ? relu4(v) : v;
                    *(float4*)&shr[w][d0] = r;
                    __syncwarp();
                    // warm next hop's weights while this matvec runs
                    if (mp.w >= 0 && mp.z == 0)
                        prefetch_l2_full((const char*)(ew + (long long)mp.w * DIM * DIM), c);
                    float4 m = *(const float4*)(ebias + eid * DIM + d0);
                    mv_stream<DIM, 16>((const float4*)(ew + (long long)eid * DIM * DIM + d0),
                                       shr[w], m);
                    if (mp.y == 1) {                   // single child: no handshake
                        const float4 bv = __ldcg((const float4*)&g_vacc[g][par][d0]);
                        v = make_float4(bv.x + m.x, bv.y + m.y, bv.z + m.z, bv.w + m.w);
                    } else {
                        float* dst = &g_vacc[g][par][d0];
                        atomicAdd(dst + 0, m.x); atomicAdd(dst + 1, m.y);
                        atomicAdd(dst + 2, m.z); atomicAdd(dst + 3, m.w);
                        __syncwarp();                  // REDGs ordered before bump
                        const int old = bump_arrive(&g_cdone[g][par], c);
                        if (old != mp.y - 1) break;    // not last: die
                        __syncwarp();
                        v = __ldcg((const float4*)&g_vacc[g][par][d0]);
                    }
                }
                internal = true;                       // continued nodes are internal
                n = par; mt = mp;
            }
        }
    }

    // ================= phase 2: matrix chain (g = b>>4, row e) =============
    {
        const int g = b >> 4;
        const int e = (b & 15) * 8 + w;
        {   // warm L2 with this row's step-0 weights while waiting
            const char* wb = (const char*)(ew + (long long)e * DIM * DIM);
#pragma unroll
            for (int i = 0; i < 16; ++i)
                asm volatile("prefetch.global.L2 [%0];" :: "l"(wb + ((c + (i << 5)) << 7)));
        }
        const int plen = g_plen[g];
        wait_ge(&g_pathdone[g], 1);            // v(pos) ready

        const int p0 = g_path[g][0];
        float4 r0 = __ldcg((const float4*)&g_bvec[g][p0][d0]);
        if (__ldg(&g_meta[g][p0].y) > 0) r0 = relu4(r0);
        *(float4*)&shr[w][d0] = r0;
        __syncwarp();

        // step 0: per-row weight matrix W[e]
        float4 m = *(const float4*)(ebias + e * DIM + d0);
        mv_stream<DIM, 16>((const float4*)(ew + (long long)e * DIM * DIM + d0), shr[w], m);

        // steps 1..plen-1: shared W per (graph, step), gated on path progress
        for (int s = 1; s < plen; ++s) {
            const int a = g_path[g][s];
            const int eid = __ldg(&g_meta[g][a].w);
            prefetch_l1_slice((const char*)(ew + (long long)eid * DIM * DIM), w, c);
            wait_ge(&g_pathdone[g], s + 1);
            const float4 bv = __ldcg((const float4*)&g_bvec[g][a][d0]);
            const float4 r = make_float4(fmaxf(bv.x + m.x, 0.f), fmaxf(bv.y + m.y, 0.f),
                                         fmaxf(bv.z + m.z, 0.f), fmaxf(bv.w + m.w, 0.f));
            __syncwarp();                      // all lanes done reading prior shr
            *(float4*)&shr[w][d0] = r;
            __syncwarp();
            m = *(const float4*)(ebias + eid * DIM + d0);
            mv_stream<DIM, 16>((const float4*)(ew + (long long)eid * DIM * DIM + d0),
                               shr[w], m);
        }

        const float4 s4 = *(const float4*)(sew + d0);
        const float s = warp_sum(m.x * s4.x + m.y * s4.y + m.z * s4.z + m.w * s4.w);
        if (c == 0) out[g * NE + e] = g_dscore + s;
    }
}

extern "C" void kernel_launch(void* const* d_in, const int* in_sizes, int n_in,
                              void* d_out, int out_size) {
    const int*   data   = (const int*)d_in[0];
    // d_in[1] = types (unused: single data_type)
    const int*   graphs = (const int*)d_in[2];
    const int*   edges  = (const int*)d_in[3];
    const int*   posp   = (const int*)d_in[4];
    const float* vecs   = (const float*)d_in[5];
    const float* dW     = (const float*)d_in[6];
    const float* db     = (const float*)d_in[7];
    const float* ew     = (const float*)d_in[8];
    const float* ebias  = (const float*)d_in[9];
    const float* sew    = (const float*)d_in[10];
    const float* sdw    = (const float*)d_in[11];
    const float* sbias  = (const float*)d_in[12];
    float* out = (float*)d_out;

    k_base<<<NG + NN, 128>>>(graphs, edges, posp, data, vecs, dW, db, sdw, sbias);
    k_main<<<NN, 256>>>(ew, ebias, sew, out);
}

// round 13
// speedup vs baseline: 1.5358x; 1.0406x over previous
#include <cuda_runtime.h>

#define NG  8     // graphs
#define NN  128   // nodes
#define DIM 128   // embedding dim
#define NE  128   // edge types
#define VEC 300   // word-vec dim

// ---- scratch (device globals; no allocations allowed) ----
__device__ __align__(16) float g_vacc[NG][NN][DIM];
__device__ __align__(16) float g_bvec[NG][NN][DIM];
__device__ int   g_parent[NG][NN];
__device__ int   g_ccount[NG][NN];
__device__ int   g_cdone[NG][NN];
__device__ int   g_onpath[NG][NN];
__device__ int   g_path[NG][NN];
__device__ int   g_plen[NG];
__device__ int   g_edges_eff[NN];
__device__ int   g_pathdone[NG];
__device__ float g_dscore;

// ---- acquire/release primitives ----
__device__ __forceinline__ int ld_acquire(const int* p) {
    int v;
    asm volatile("ld.acquire.gpu.global.u32 %0, [%1];" : "=r"(v) : "l"(p) : "memory");
    return v;
}
__device__ __forceinline__ void red_release_add(int* p, int v) {
    asm volatile("red.release.gpu.global.add.u32 [%0], %1;" :: "l"(p), "r"(v) : "memory");
}
// ALL lanes spin: every lane carries its own acquire edge (hot spin, used on
// the tree critical path).
__device__ __forceinline__ void wait_ge(const int* p, int need) {
    while (ld_acquire(p) < need) { }
    __syncwarp();
}
// Backoff poll (phase-2 gating: runs while tree warps compute on the same SM;
// nanosleep keeps these pollers out of the issue slots).
__device__ __forceinline__ void wait_ge_bk(const int* p, int need) {
    while (ld_acquire(p) < need) { __nanosleep(64); }
    __syncwarp();
}

// ---------------------------------------------------------------------------
// Streaming matvec: thread owns 4 consecutive output dims (d0 = 4*lane).
// W4 points at W[0][d0] (row stride DIM floats). Double-buffered register
// chunks -> 2*CH LDG.128 in flight per thread (needs launch_bounds(...,1)).
// ---------------------------------------------------------------------------
template<int K, int CH>
__device__ __forceinline__ void mv_stream(const float4* __restrict__ W4,
                                          const float* __restrict__ r,
                                          float4& m) {
    constexpr int STEP = 2 * CH;
    constexpr int NCH  = (K + STEP - 1) / STEP;
    float4 A[CH], B[CH];
#pragma unroll
    for (int i = 0; i < CH; ++i)
        A[i] = (i < K) ? W4[i * (DIM / 4)] : make_float4(0.f, 0.f, 0.f, 0.f);
#pragma unroll
    for (int o = 0; o < NCH; ++o) {
        const int kb = o * STEP, k2 = kb + CH, k3 = kb + STEP;
#pragma unroll
        for (int i = 0; i < CH; ++i)
            B[i] = (k2 + i < K) ? W4[(k2 + i) * (DIM / 4)] : make_float4(0.f, 0.f, 0.f, 0.f);
#pragma unroll
        for (int i = 0; i < CH; ++i)
            if (kb + i < K) {
                const float rk = r[kb + i];
                m.x += rk * A[i].x; m.y += rk * A[i].y;
                m.z += rk * A[i].z; m.w += rk * A[i].w;
            }
#pragma unroll
        for (int i = 0; i < CH; ++i)
            A[i] = (k3 + i < K) ? W4[(k3 + i) * (DIM / 4)] : make_float4(0.f, 0.f, 0.f, 0.f);
#pragma unroll
        for (int i = 0; i < CH; ++i)
            if (k2 + i < K) {
                const float rk = r[k2 + i];
                m.x += rk * B[i].x; m.y += rk * B[i].y;
                m.z += rk * B[i].z; m.w += rk * B[i].w;
            }
    }
}

__device__ __forceinline__ float warp_sum(float s) {
#pragma unroll
    for (int o = 16; o; o >>= 1) s += __shfl_down_sync(0xffffffffu, s, o);
    return s;
}

__device__ __forceinline__ float4 relu4(float4 v) {
    return make_float4(fmaxf(v.x, 0.f), fmaxf(v.y, 0.f), fmaxf(v.z, 0.f), fmaxf(v.w, 0.f));
}

// Cooperative 8-warp L1 prefetch of one 64KB matrix (2 lines per lane).
__device__ __forceinline__ void prefetch_l1_slice(const char* base, int w, int c) {
    const char* p = base + (((w << 6) + c) << 7);
    asm volatile("prefetch.global.L1 [%0];" :: "l"(p));
    asm volatile("prefetch.global.L1 [%0];" :: "l"(p + (32 << 7)));
}

// ---------------------------------------------------------------------------
// Setup: one block per graph — structure (counts, parents, path, onpath) and
// per-replay resets (counters, flags, vacc zero).
// ---------------------------------------------------------------------------
__global__ __launch_bounds__(128, 1) void k_setup(
        const int* __restrict__ graphs, const int* __restrict__ edges,
        const int* __restrict__ posp) {
    const int t = threadIdx.x;
    const int pos = posp[0];
    const int g = blockIdx.x;
    g_ccount[g][t] = 0;
    g_cdone[g][t]  = 0;
    g_onpath[g][t] = 0;
    for (int n = 0; n < NN; ++n) g_vacc[g][n][t] = 0.f;
    if (g == 0) g_edges_eff[t] = (t == pos) ? -1 : edges[t];
    if (t == 0) g_pathdone[g] = 0;
    __syncthreads();
    const int off = graphs[g * NN + t];
    const int par = (off == 0) ? -1 : (t + off);
    g_parent[g][t] = par;
    if (par >= 0) atomicAdd(&g_ccount[g][par], 1);
    if (t == 0) {
        int cur = pos, len = 0;
        while (len < NN) {
            g_path[g][len++] = cur;
            g_onpath[g][cur] = 1;
            const int o = graphs[g * NN + cur];
            if (o == 0) break;
            cur += o;
        }
        g_plen[g] = len;
    }
}

// ---------------------------------------------------------------------------
// Fused main kernel: 128 blocks x 256 threads, 1 block/SM -> all resident.
// Phase 0: block n computes base[n] = vecs[data[n]] @ dW + db via 8-warp
//   k-split into shared sh_base. The pos block also stores d_score (made
//   visible through its phase-1 release; pos is path[0] of every graph, so
//   every pathdone acquire happens-after it).
// Phase 1: warp (block=n, g=w) owns tree task (n,g): L2-prefetch its W during
//   the wait, wait ccount child signals (hot spin), form v = base + vacc,
//   then either store bvec + release-bump pathdone (path node) or matvec +
//   atomicAdd into the parent's vacc; release-signal the parent counter.
// Phase 2 (overlapped with the tree): warp (g=b>>4, row e=(b&15)*8+w) walks
//   the pos->root chain; step s gated on pathdone >= s+1 with nanosleep
//   backoff. Path nodes finish in path order during the climb, so the chain
//   tracks the tree and only the post-root step is exposed.
// ---------------------------------------------------------------------------
__global__ __launch_bounds__(256, 1) void k_main(
        const int* __restrict__ data,  const float* __restrict__ vecs,
        const float* __restrict__ dW,  const float* __restrict__ db,
        const float* __restrict__ sdw, const float* __restrict__ sbias,
        const float* __restrict__ ew,  const float* __restrict__ ebias,
        const float* __restrict__ sew, const int* __restrict__ posp,
        float* __restrict__ out) {
    __shared__ __align__(16) float shv[304];
    __shared__ __align__(16) float part[8][DIM];
    __shared__ __align__(16) float sh_base[DIM];
    __shared__ __align__(16) float shr[8][DIM];
    const int t = threadIdx.x, w = t >> 5, c = t & 31;
    const int d0 = c * 4;
    const int b = blockIdx.x;
    const int pos = posp[0];

    // ================= phase 0: base[n] for this block's node ==============
    {
        const int n = b;
        const float* vr = vecs + (long long)data[n] * VEC;
        for (int i = t; i < 304; i += 256) shv[i] = (i < VEC) ? vr[i] : 0.f;
        __syncthreads();
        const int k0 = (w * VEC) >> 3, k1 = ((w + 1) * VEC) >> 3;   // 37/38 rows
        float4 acc = make_float4(0.f, 0.f, 0.f, 0.f);
#pragma unroll 8
        for (int k = k0; k < k1; ++k) {
            const float rv = shv[k];
            const float4 wv = *(const float4*)(dW + (long long)k * DIM + d0);
            acc.x += rv * wv.x; acc.y += rv * wv.y;
            acc.z += rv * wv.z; acc.w += rv * wv.w;
        }
        *(float4*)&part[w][d0] = acc;
        __syncthreads();
        if (w == 0) {
            float4 m = *(const float4*)(db + d0);
#pragma unroll
            for (int ww = 0; ww < 8; ++ww) {
                const float4 p = *(const float4*)&part[ww][d0];
                m.x += p.x; m.y += p.y; m.z += p.z; m.w += p.w;
            }
            *(float4*)&sh_base[d0] = m;
            if (n == pos) {
                const float4 s4 = *(const float4*)(sdw + d0);
                const float s = warp_sum(m.x * s4.x + m.y * s4.y + m.z * s4.z + m.w * s4.w);
                if (c == 0) g_dscore = sbias[0] + s;   // ordered by releases below
            }
        }
        __syncthreads();
    }

    // ================= phase 1: vector task (n = block, g = warp) ==========
    {
        const int n = b;
        const int g = w;
        const int need   = g_ccount[g][n];
        const int par    = g_parent[g][n];
        const int onpath = g_onpath[g][n];
        const int eid    = g_edges_eff[n];
        const float* W = ew + (long long)eid * DIM * DIM;
        if (!onpath && need > 0) {
            // pull this task's weights toward L2 while waiting
            const char* wb = (const char*)W;
#pragma unroll
            for (int i = 0; i < 16; ++i)
                asm volatile("prefetch.global.L2 [%0];" :: "l"(wb + ((c + (i << 5)) << 7)));
        }
        if (need > 0) wait_ge(&g_cdone[g][n], need);
        float4 v = *(const float4*)&sh_base[d0];
        if (need > 0) {
            const float4 va = __ldcg((const float4*)&g_vacc[g][n][d0]);
            v.x += va.x; v.y += va.y; v.z += va.z; v.w += va.w;
        }
        if (onpath) {
            *(float4*)&g_bvec[g][n][d0] = v;
            __syncwarp();
            if (c == 0) {
                red_release_add(&g_pathdone[g], 1);   // orders the bvec store
                if (par >= 0) red_release_add(&g_cdone[g][par], 1);
            }
        } else {
            if (need > 0) v = relu4(v);       // relu only for internal nodes
            *(float4*)&shr[w][d0] = v;
            __syncwarp();
            float4 m = *(const float4*)(ebias + eid * DIM + d0);
            mv_stream<DIM, 16>((const float4*)(W + d0), shr[w], m);
            float* dst = &g_vacc[g][par][d0];
            atomicAdd(dst + 0, m.x); atomicAdd(dst + 1, m.y);
            atomicAdd(dst + 2, m.z); atomicAdd(dst + 3, m.w);
            __syncwarp();
            if (c == 0) red_release_add(&g_cdone[g][par], 1);
        }
        __syncwarp();
    }

    // ================= phase 2: matrix chain (g = b>>4, row e) =============
    {
        const int g = b >> 4;
        const int e = (b & 15) * 8 + w;
        {
            // warm L2 with this row's step-0 weights while waiting
            const char* wb = (const char*)(ew + (long long)e * DIM * DIM);
#pragma unroll
            for (int i = 0; i < 16; ++i)
                asm volatile("prefetch.global.L2 [%0];" :: "l"(wb + ((c + (i << 5)) << 7)));
        }
        const int plen = g_plen[g];            // from k_setup (prior launch)
        const int p0   = g_path[g][0];
        wait_ge_bk(&g_pathdone[g], 1);         // v(pos) ready

        float4 r0 = __ldcg((const float4*)&g_bvec[g][p0][d0]);
        if (g_ccount[g][p0] > 0) r0 = relu4(r0);
        *(float4*)&shr[w][d0] = r0;
        __syncwarp();

        // step 0: per-row weight matrix W[e]
        float4 m = *(const float4*)(ebias + e * DIM + d0);
        mv_stream<DIM, 16>((const float4*)(ew + (long long)e * DIM * DIM + d0), shr[w], m);

        // steps 1..plen-1: shared W per (graph, step), gated on path progress
        for (int s = 1; s < plen; ++s) {
            const int a   = g_path[g][s];
            const int eid = g_edges_eff[a];
            prefetch_l1_slice((const char*)(ew + (long long)eid * DIM * DIM), w, c);
            wait_ge_bk(&g_pathdone[g], s + 1);
            const float4 bv = __ldcg((const float4*)&g_bvec[g][a][d0]);
            const float4 r = make_float4(fmaxf(bv.x + m.x, 0.f), fmaxf(bv.y + m.y, 0.f),
                                         fmaxf(bv.z + m.z, 0.f), fmaxf(bv.w + m.w, 0.f));
            __syncwarp();                      // all lanes done reading prior shr
            *(float4*)&shr[w][d0] = r;
            __syncwarp();
            m = *(const float4*)(ebias + eid * DIM + d0);
            mv_stream<DIM, 16>((const float4*)(ew + (long long)eid * DIM * DIM + d0), shr[w], m);
        }

        const float4 s4 = *(const float4*)(sew + d0);
        const float s = warp_sum(m.x * s4.x + m.y * s4.y + m.z * s4.z + m.w * s4.w);
        if (c == 0) out[g * NE + e] = __ldcg(&g_dscore) + s;
    }
}

extern "C" void kernel_launch(void* const* d_in, const int* in_sizes, int n_in,
                              void* d_out, int out_size) {
    const int*   data   = (const int*)d_in[0];
    // d_in[1] = types (unused: single data_type)
    const int*   graphs = (const int*)d_in[2];
    const int*   edges  = (const int*)d_in[3];
    const int*   posp   = (const int*)d_in[4];
    const float* vecs   = (const float*)d_in[5];
    const float* dW     = (const float*)d_in[6];
    const float* db     = (const float*)d_in[7];
    const float* ew     = (const float*)d_in[8];
    const float* ebias  = (const float*)d_in[9];
    const float* sew    = (const float*)d_in[10];
    const float* sdw    = (const float*)d_in[11];
    const float* sbias  = (const float*)d_in[12];
    float* out = (float*)d_out;

    k_setup<<<NG, 128>>>(graphs, edges, posp);
    k_main<<<NN, 256>>>(data, vecs, dW, db, sdw, sbias,
                        ew, ebias, sew, posp, out);
}